// round 3
// baseline (speedup 1.0000x reference)
#include <cuda_runtime.h>

#define TT 300
// SLAYER constants
#define D_SR 0.9048374180359595f    // exp(-Ts/tauSr), tauSr=10
#define B_SR 0.2718281828459045f    // e*Ts/tauSr
#define D_RF 0.3678794411714423f    // exp(-Ts/tauRef), tauRef=1
#define A_RF -54.365636569180902f   // -scaleRef*theta*e*Ts/tauRef
#define THETA 10.0f
#define PGAIN 11.0f                 // 1.1*theta

// ---- scratch arenas (time-major [t][n][c][h][w]) ----
// A: v1[300x100352] / v3[300x50176] / psp5[300x25088]
// B: psp1[300x100352] / psp3[300x50176]
// C: psp2[300x25088]  / v5[300x25088]
// D: psp0[300x7200] / psp4[300x12544]
__device__ float g_bufA[30105600];
__device__ float g_bufB[30105600];
__device__ float g_bufC[7526400];
__device__ float g_bufD[3763200];
__device__ float g_bufY[24000];

// --- exact-order recurrence steps (no fma contraction, matching XLA) ---
// psp step: q = d*(q+p); out = B*q; p = d*p + x
__device__ __forceinline__ float psp_step(float x, float& p, float& q) {
    q = __fmul_rn(D_SR, __fadd_rn(q, p));
    float out = __fmul_rn(B_SR, q);
    p = __fadd_rn(__fmul_rn(D_SR, p), x);
    return out;
}
// spike step: q = d*(q+p); s = (u + A*q >= theta); p = d*p + s
__device__ __forceinline__ float spike_step(float u, float& p, float& q) {
    q = __fmul_rn(D_RF, __fadd_rn(q, p));
    float m = __fadd_rn(u, __fmul_rn(A_RF, q));
    float s = (m >= THETA) ? 1.0f : 0.0f;
    p = __fadd_rn(__fmul_rn(D_RF, p), s);
    return s;
}

// K0: psp of the raw input. in [j=7200][t] (t contiguous) -> time-major psp0 in bufD.
__global__ void k_psp0(const float* __restrict__ in) {
    int j = blockIdx.x * blockDim.x + threadIdx.x;
    if (j >= 7200) return;
    float p = 0.f, q = 0.f;
    const float* xp = in + (size_t)j * TT;
    for (int t = 0; t < TT; t++) {
        g_bufD[(size_t)t * 7200 + j] = psp_step(xp[t], p, q);
    }
}

// Fused spike(v) -> psp(s): per neuron, reads drive v, writes psp of spikes.
__global__ void k_spike_psp(const float* __restrict__ v, float* __restrict__ po, int nn) {
    int i = blockIdx.x * blockDim.x + threadIdx.x;
    if (i >= nn) return;
    float ps = 0.f, qs = 0.f, pp = 0.f, qq = 0.f;
    for (int t = 0; t < TT; t++) {
        float s = spike_step(v[(size_t)t * nn + i], ps, qs);
        po[(size_t)t * nn + i] = psp_step(s, pp, qq);
    }
}

// Fused pool(psp_in)*gain -> spike -> psp: reads 4 psp values per step.
__global__ void k_pool_spike_psp(const float* __restrict__ pin, float* __restrict__ po,
                                 int C, int Ho, int Wo, int nn_in, int nn_out) {
    int i = blockIdx.x * blockDim.x + threadIdx.x;
    if (i >= nn_out) return;
    int per = C * Ho * Wo;
    int n = i / per;
    int rem = i - n * per;
    int c = rem / (Ho * Wo);
    int r2 = rem - c * (Ho * Wo);
    int oh = r2 / Wo, ow = r2 - oh * Wo;
    int Wi = 2 * Wo;
    size_t base = ((size_t)(n * C + c) * (2 * Ho) + 2 * oh) * Wi + 2 * ow;
    float ps = 0.f, qs = 0.f, pp = 0.f, qq = 0.f;
    for (int t = 0; t < TT; t++) {
        const float* bp = pin + (size_t)t * nn_in + base;
        float u = __fmul_rn(PGAIN,
            __fadd_rn(__fadd_rn(bp[0], bp[1]), __fadd_rn(bp[Wi], bp[Wi + 1])));
        float s = spike_step(u, ps, qs);
        po[(size_t)t * nn_out + i] = psp_step(s, pp, qq);
    }
}

// K1: conv1 (1->16, 5x5, pad1, 30->28) per timestep on psp0. D -> A.
__global__ void __launch_bounds__(448) k_conv1(const float* __restrict__ w) {
    __shared__ float xs[900];
    __shared__ float ws[400];
    int b = blockIdx.x;
    int t = b >> 3;
    int n = b & 7;
    const float* xp = g_bufD + (size_t)t * 7200 + n * 900;
    for (int i = threadIdx.x; i < 900; i += 448) xs[i] = xp[i];
    for (int i = threadIdx.x; i < 400; i += 448) ws[i] = w[i];
    __syncthreads();
    int o = threadIdx.x / 28;
    int oh = threadIdx.x % 28;
    float acc[28];
#pragma unroll
    for (int p = 0; p < 28; p++) acc[p] = 0.f;
#pragma unroll
    for (int kh = 0; kh < 5; kh++) {
        int ih = oh - 1 + kh;
        if ((unsigned)ih < 30u) {
            float r[32];
            r[0] = 0.f; r[31] = 0.f;
#pragma unroll
            for (int j = 0; j < 30; j++) r[j + 1] = xs[ih * 30 + j];
#pragma unroll
            for (int kw = 0; kw < 5; kw++) {
                float wv = ws[o * 25 + kh * 5 + kw];
#pragma unroll
                for (int p = 0; p < 28; p++) acc[p] = fmaf(wv, r[p + kw], acc[p]);
            }
        }
    }
    float* vp = g_bufA + (size_t)t * 100352 + ((n * 16 + o) * 28 + oh) * 28;
#pragma unroll
    for (int p = 0; p < 28; p++) vp[p] = acc[p];
}

// K2: conv2 (16->32, 3x3, pad1, 14x14) per timestep: C(psp2) -> A(v3).
__global__ void __launch_bounds__(448) k_conv2(const float* __restrict__ w) {
    __shared__ float xs[3136];   // 16*14*14
    __shared__ float ws[4608];   // 32*16*9
    int b = blockIdx.x;
    int t = b >> 3;
    int n = b & 7;
    const float* xp = g_bufC + (size_t)t * 25088 + n * 3136;
    for (int i = threadIdx.x; i < 3136; i += 448) xs[i] = xp[i];
    for (int i = threadIdx.x; i < 4608; i += 448) ws[i] = w[i];
    __syncthreads();
    int o = threadIdx.x / 14, oh = threadIdx.x % 14;
    float acc[14];
#pragma unroll
    for (int p = 0; p < 14; p++) acc[p] = 0.f;
    for (int c = 0; c < 16; c++) {
#pragma unroll
        for (int kh = 0; kh < 3; kh++) {
            int ih = oh - 1 + kh;
            float r[16];
            r[0] = 0.f; r[15] = 0.f;
            if ((unsigned)ih < 14u) {
#pragma unroll
                for (int j = 0; j < 14; j++) r[j + 1] = xs[c * 196 + ih * 14 + j];
            } else {
#pragma unroll
                for (int j = 0; j < 14; j++) r[j + 1] = 0.f;
            }
#pragma unroll
            for (int kw = 0; kw < 3; kw++) {
                float wv = ws[((o * 16 + c) * 3 + kh) * 3 + kw];
#pragma unroll
                for (int p = 0; p < 14; p++) acc[p] = fmaf(wv, r[p + kw], acc[p]);
            }
        }
    }
    float* vp = g_bufA + (size_t)t * 50176 + ((n * 32 + o) * 14 + oh) * 14;
#pragma unroll
    for (int p = 0; p < 14; p++) vp[p] = acc[p];
}

// K3: conv3 (32->64, 3x3, pad1, 7x7) per timestep: D(psp4) -> C(v5).
extern __shared__ float dynsm[];
__global__ void __launch_bounds__(224) k_conv3(const float* __restrict__ w) {
    float* ws = dynsm;           // 18432 floats
    float* xs = dynsm + 18432;   // 1568 floats
    int b = blockIdx.x;
    int t = b >> 3;
    int n = b & 7;
    const float* xp = g_bufD + (size_t)t * 12544 + n * 1568;
    for (int i = threadIdx.x; i < 18432; i += 224) ws[i] = w[i];
    for (int i = threadIdx.x; i < 1568; i += 224) xs[i] = xp[i];
    __syncthreads();
    int o = threadIdx.x / 7, oh = threadIdx.x % 7;
    float acc0[7], acc1[7];
#pragma unroll
    for (int p = 0; p < 7; p++) { acc0[p] = 0.f; acc1[p] = 0.f; }
    for (int c = 0; c < 32; c++) {
#pragma unroll
        for (int kh = 0; kh < 3; kh++) {
            int ih = oh - 1 + kh;
            float r[9];
            r[0] = 0.f; r[8] = 0.f;
            if ((unsigned)ih < 7u) {
#pragma unroll
                for (int j = 0; j < 7; j++) r[j + 1] = xs[c * 49 + ih * 7 + j];
            } else {
#pragma unroll
                for (int j = 0; j < 7; j++) r[j + 1] = 0.f;
            }
#pragma unroll
            for (int kw = 0; kw < 3; kw++) {
                float w0 = ws[((o * 32 + c) * 3 + kh) * 3 + kw];
                float w1 = ws[(((o + 32) * 32 + c) * 3 + kh) * 3 + kw];
#pragma unroll
                for (int p = 0; p < 7; p++) {
                    acc0[p] = fmaf(w0, r[p + kw], acc0[p]);
                    acc1[p] = fmaf(w1, r[p + kw], acc1[p]);
                }
            }
        }
    }
    float* vp0 = g_bufC + (size_t)t * 25088 + ((n * 64 + o) * 7 + oh) * 7;
    float* vp1 = g_bufC + (size_t)t * 25088 + ((n * 64 + o + 32) * 7 + oh) * 7;
#pragma unroll
    for (int p = 0; p < 7; p++) { vp0[p] = acc0[p]; vp1[p] = acc1[p]; }
}

// K4: dense head per timestep on psp5 floats: A -> Y[t][n][o].
__global__ void __launch_bounds__(256) k_fc(const float* __restrict__ w) {
    __shared__ float red[256];
    int b = blockIdx.x;
    int t = b >> 3;
    int n = b & 7;
    const float* xp = g_bufA + (size_t)t * 25088 + n * 3136;
    float acc[10];
#pragma unroll
    for (int o = 0; o < 10; o++) acc[o] = 0.f;
    for (int j = threadIdx.x; j < 3136; j += 256) {
        float xv = xp[j];
#pragma unroll
        for (int o = 0; o < 10; o++) acc[o] = fmaf(xv, w[o * 3136 + j], acc[o]);
    }
#pragma unroll
    for (int o = 0; o < 10; o++) {
        red[threadIdx.x] = acc[o];
        __syncthreads();
        for (int st = 128; st > 0; st >>= 1) {
            if (threadIdx.x < st) red[threadIdx.x] += red[threadIdx.x + st];
            __syncthreads();
        }
        if (threadIdx.x == 0) g_bufY[(size_t)t * 80 + n * 10 + o] = red[0];
        __syncthreads();
    }
}

// K5: final spike scan (no trailing psp) over 80 output neurons -> [8,10,300]
__global__ void k_spike_out(float* __restrict__ out) {
    int i = threadIdx.x;
    if (i >= 80) return;
    float ps = 0.f, qs = 0.f;
    for (int t = 0; t < TT; t++) {
        out[i * 300 + t] = spike_step(g_bufY[t * 80 + i], ps, qs);
    }
}

extern "C" void kernel_launch(void* const* d_in, const int* in_sizes, int n_in,
                              void* d_out, int out_size) {
    const float* x  = (const float*)d_in[0];   // [8,1,30,30,300]
    const float* w1 = (const float*)d_in[1];   // [16,1,5,5]
    const float* w2 = (const float*)d_in[2];   // [32,16,3,3]
    const float* w3 = (const float*)d_in[3];   // [64,32,3,3]
    const float* wf = (const float*)d_in[4];   // [10,64,7,7]
    float* out = (float*)d_out;

    float *bufA, *bufB, *bufC, *bufD;
    cudaGetSymbolAddress((void**)&bufA, g_bufA);
    cudaGetSymbolAddress((void**)&bufB, g_bufB);
    cudaGetSymbolAddress((void**)&bufC, g_bufC);
    cudaGetSymbolAddress((void**)&bufD, g_bufD);

    cudaFuncSetAttribute(k_conv3, cudaFuncAttributeMaxDynamicSharedMemorySize, 80000);

    k_psp0<<<(7200 + 127) / 128, 128>>>(x);                          // x -> D (psp0)
    k_conv1<<<2400, 448>>>(w1);                                      // D -> A (v1)
    k_spike_psp<<<(100352 + 255) / 256, 256>>>(bufA, bufB, 100352);  // A -> B (psp1)
    k_pool_spike_psp<<<(25088 + 255) / 256, 256>>>(bufB, bufC,
                                       16, 14, 14, 100352, 25088);   // B -> C (psp2)
    k_conv2<<<2400, 448>>>(w2);                                      // C -> A (v3)
    k_spike_psp<<<(50176 + 255) / 256, 256>>>(bufA, bufB, 50176);    // A -> B (psp3)
    k_pool_spike_psp<<<(12544 + 255) / 256, 256>>>(bufB, bufD,
                                       32, 7, 7, 50176, 12544);      // B -> D (psp4)
    k_conv3<<<2400, 224, 80000>>>(w3);                               // D -> C (v5)
    k_spike_psp<<<(25088 + 255) / 256, 256>>>(bufC, bufA, 25088);    // C -> A (psp5)
    k_fc<<<2400, 256>>>(wf);                                         // A -> Y
    k_spike_out<<<1, 128>>>(out);                                    // Y -> out
}

// round 5
// speedup vs baseline: 1.3160x; 1.3160x over previous
#include <cuda_runtime.h>

#define TT 300
// SLAYER constants
#define D_SR 0.9048374180359595f    // exp(-Ts/tauSr), tauSr=10
#define B_SR 0.2718281828459045f    // e*Ts/tauSr
#define D_RF 0.3678794411714423f    // exp(-Ts/tauRef), tauRef=1
#define A_RF -54.365636569180902f   // -scaleRef*theta*e*Ts/tauRef
#define THETA 10.0f
#define PGAIN 11.0f                 // 1.1*theta

// ---- scratch arenas (time-major [t][n][c][h][w]) ----
// A: v1[300x100352] / v3[300x50176] / psp5[300x25088]
// C: psp2[300x25088]  / v5[300x25088]
// D: psp0[300x7200] / psp4[300x12544]
__device__ float g_bufA[30105600];
__device__ float g_bufC[7526400];
__device__ float g_bufD[3763200];
__device__ float g_bufY[24000];

// --- exact-order recurrence steps (no fma contraction, matching XLA) ---
__device__ __forceinline__ float psp_step(float x, float& p, float& q) {
    q = __fmul_rn(D_SR, __fadd_rn(q, p));
    float out = __fmul_rn(B_SR, q);
    p = __fadd_rn(__fmul_rn(D_SR, p), x);
    return out;
}
__device__ __forceinline__ float spike_step(float u, float& p, float& q) {
    q = __fmul_rn(D_RF, __fadd_rn(q, p));
    float m = __fadd_rn(u, __fmul_rn(A_RF, q));
    float s = (m >= THETA) ? 1.0f : 0.0f;
    p = __fadd_rn(__fmul_rn(D_RF, p), s);
    return s;
}

// K0: psp of raw input. in [j=7200][t] -> time-major psp0 in bufD. float4 + prefetch.
__global__ void k_psp0(const float* __restrict__ in) {
    int j = blockIdx.x * blockDim.x + threadIdx.x;
    if (j >= 7200) return;
    const float4* xp = reinterpret_cast<const float4*>(in + (size_t)j * TT);
    float p = 0.f, q = 0.f;
    float4 cur = xp[0];
    for (int tb = 0; tb < 75; tb++) {
        float4 nxt;
        if (tb < 74) nxt = xp[tb + 1];
        g_bufD[(size_t)(4 * tb + 0) * 7200 + j] = psp_step(cur.x, p, q);
        g_bufD[(size_t)(4 * tb + 1) * 7200 + j] = psp_step(cur.y, p, q);
        g_bufD[(size_t)(4 * tb + 2) * 7200 + j] = psp_step(cur.z, p, q);
        g_bufD[(size_t)(4 * tb + 3) * 7200 + j] = psp_step(cur.w, p, q);
        cur = nxt;
    }
}

// Fused: 4 parent drives v -> [spike -> psp] x4 -> pool*gain -> spike -> psp.
// One thread per pooled neuron; 5 independent chains for ILP; chunked
// double-buffer prefetch (CH=10 steps, 40 outstanding loads per chunk).
__global__ void k_fused_pool(const float* __restrict__ v, float* __restrict__ po,
                             int C, int Ho, int Wo, int nn_in, int nn_out) {
    int i = blockIdx.x * blockDim.x + threadIdx.x;
    if (i >= nn_out) return;
    int per = C * Ho * Wo;
    int n = i / per;
    int rem = i - n * per;
    int c = rem / (Ho * Wo);
    int r2 = rem - c * (Ho * Wo);
    int oh = r2 / Wo, ow = r2 - oh * Wo;
    int Wi = 2 * Wo;
    size_t base = ((size_t)(n * C + c) * (2 * Ho) + 2 * oh) * Wi + 2 * ow;

    float ps[4], qs[4], pp[4], qq[4];
#pragma unroll
    for (int jj = 0; jj < 4; jj++) { ps[jj] = 0.f; qs[jj] = 0.f; pp[jj] = 0.f; qq[jj] = 0.f; }
    float psO = 0.f, qsO = 0.f, ppO = 0.f, qqO = 0.f;

    const int CH = 10;
    float cur[4 * CH], nxt[4 * CH];
#pragma unroll
    for (int k = 0; k < CH; k++) {
        const float* bp = v + (size_t)k * nn_in + base;
        cur[4 * k + 0] = bp[0];
        cur[4 * k + 1] = bp[1];
        cur[4 * k + 2] = bp[Wi];
        cur[4 * k + 3] = bp[Wi + 1];
    }
    for (int tb = 0; tb < TT / CH; tb++) {
        if (tb + 1 < TT / CH) {
#pragma unroll
            for (int k = 0; k < CH; k++) {
                const float* bp = v + (size_t)((tb + 1) * CH + k) * nn_in + base;
                nxt[4 * k + 0] = bp[0];
                nxt[4 * k + 1] = bp[1];
                nxt[4 * k + 2] = bp[Wi];
                nxt[4 * k + 3] = bp[Wi + 1];
            }
        }
#pragma unroll
        for (int k = 0; k < CH; k++) {
            float pv[4];
#pragma unroll
            for (int jj = 0; jj < 4; jj++) {
                float s = spike_step(cur[4 * k + jj], ps[jj], qs[jj]);
                pv[jj] = psp_step(s, pp[jj], qq[jj]);
            }
            float u = __fmul_rn(PGAIN,
                __fadd_rn(__fadd_rn(pv[0], pv[1]), __fadd_rn(pv[2], pv[3])));
            float s2 = spike_step(u, psO, qsO);
            po[(size_t)(tb * CH + k) * nn_out + i] = psp_step(s2, ppO, qqO);
        }
#pragma unroll
        for (int k = 0; k < 4 * CH; k++) cur[k] = nxt[k];
    }
}

// Fused spike(v) -> psp(s), chunked double-buffer prefetch.
__global__ void k_spike_psp(const float* __restrict__ v, float* __restrict__ po, int nn) {
    int i = blockIdx.x * blockDim.x + threadIdx.x;
    if (i >= nn) return;
    float ps = 0.f, qs = 0.f, pp = 0.f, qq = 0.f;
    const int CH = 10;
    float cur[CH], nxt[CH];
#pragma unroll
    for (int k = 0; k < CH; k++) cur[k] = v[(size_t)k * nn + i];
    for (int tb = 0; tb < TT / CH; tb++) {
        if (tb + 1 < TT / CH) {
#pragma unroll
            for (int k = 0; k < CH; k++)
                nxt[k] = v[(size_t)((tb + 1) * CH + k) * nn + i];
        }
#pragma unroll
        for (int k = 0; k < CH; k++) {
            float s = spike_step(cur[k], ps, qs);
            po[(size_t)(tb * CH + k) * nn + i] = psp_step(s, pp, qq);
        }
#pragma unroll
        for (int k = 0; k < CH; k++) cur[k] = nxt[k];
    }
}

// K1: conv1 (1->16, 5x5, pad1, 30->28) per timestep on psp0. D -> A.
__global__ void __launch_bounds__(448) k_conv1(const float* __restrict__ w) {
    __shared__ float xs[900];
    __shared__ float ws[400];
    int b = blockIdx.x;
    int t = b >> 3;
    int n = b & 7;
    const float* xp = g_bufD + (size_t)t * 7200 + n * 900;
    for (int i = threadIdx.x; i < 900; i += 448) xs[i] = xp[i];
    for (int i = threadIdx.x; i < 400; i += 448) ws[i] = w[i];
    __syncthreads();
    int o = threadIdx.x / 28;
    int oh = threadIdx.x % 28;
    float acc[28];
#pragma unroll
    for (int p = 0; p < 28; p++) acc[p] = 0.f;
#pragma unroll
    for (int kh = 0; kh < 5; kh++) {
        int ih = oh - 1 + kh;
        if ((unsigned)ih < 30u) {
            float r[32];
            r[0] = 0.f; r[31] = 0.f;
#pragma unroll
            for (int j = 0; j < 30; j++) r[j + 1] = xs[ih * 30 + j];
#pragma unroll
            for (int kw = 0; kw < 5; kw++) {
                float wv = ws[o * 25 + kh * 5 + kw];
#pragma unroll
                for (int p = 0; p < 28; p++) acc[p] = fmaf(wv, r[p + kw], acc[p]);
            }
        }
    }
    float* vp = g_bufA + (size_t)t * 100352 + ((n * 16 + o) * 28 + oh) * 28;
#pragma unroll
    for (int p = 0; p < 28; p++) vp[p] = acc[p];
}

// K2: conv2 (16->32, 3x3, pad1, 14x14) per timestep: C(psp2) -> A(v3).
__global__ void __launch_bounds__(448) k_conv2(const float* __restrict__ w) {
    __shared__ float xs[3136];   // 16*14*14
    __shared__ float ws[4608];   // 32*16*9
    int b = blockIdx.x;
    int t = b >> 3;
    int n = b & 7;
    const float* xp = g_bufC + (size_t)t * 25088 + n * 3136;
    for (int i = threadIdx.x; i < 3136; i += 448) xs[i] = xp[i];
    for (int i = threadIdx.x; i < 4608; i += 448) ws[i] = w[i];
    __syncthreads();
    int o = threadIdx.x / 14, oh = threadIdx.x % 14;
    float acc[14];
#pragma unroll
    for (int p = 0; p < 14; p++) acc[p] = 0.f;
    for (int c = 0; c < 16; c++) {
#pragma unroll
        for (int kh = 0; kh < 3; kh++) {
            int ih = oh - 1 + kh;
            float r[16];
            r[0] = 0.f; r[15] = 0.f;
            if ((unsigned)ih < 14u) {
#pragma unroll
                for (int j = 0; j < 14; j++) r[j + 1] = xs[c * 196 + ih * 14 + j];
            } else {
#pragma unroll
                for (int j = 0; j < 14; j++) r[j + 1] = 0.f;
            }
#pragma unroll
            for (int kw = 0; kw < 3; kw++) {
                float wv = ws[((o * 16 + c) * 3 + kh) * 3 + kw];
#pragma unroll
                for (int p = 0; p < 14; p++) acc[p] = fmaf(wv, r[p + kw], acc[p]);
            }
        }
    }
    float* vp = g_bufA + (size_t)t * 50176 + ((n * 32 + o) * 14 + oh) * 14;
#pragma unroll
    for (int p = 0; p < 14; p++) vp[p] = acc[p];
}

// K3: conv3 (32->64, 3x3, pad1, 7x7) per timestep: D(psp4) -> C(v5).
extern __shared__ float dynsm[];
__global__ void __launch_bounds__(224) k_conv3(const float* __restrict__ w) {
    float* ws = dynsm;           // 18432 floats
    float* xs = dynsm + 18432;   // 1568 floats
    int b = blockIdx.x;
    int t = b >> 3;
    int n = b & 7;
    const float* xp = g_bufD + (size_t)t * 12544 + n * 1568;
    for (int i = threadIdx.x; i < 18432; i += 224) ws[i] = w[i];
    for (int i = threadIdx.x; i < 1568; i += 224) xs[i] = xp[i];
    __syncthreads();
    int o = threadIdx.x / 7, oh = threadIdx.x % 7;
    float acc0[7], acc1[7];
#pragma unroll
    for (int p = 0; p < 7; p++) { acc0[p] = 0.f; acc1[p] = 0.f; }
    for (int c = 0; c < 32; c++) {
#pragma unroll
        for (int kh = 0; kh < 3; kh++) {
            int ih = oh - 1 + kh;
            float r[9];
            r[0] = 0.f; r[8] = 0.f;
            if ((unsigned)ih < 7u) {
#pragma unroll
                for (int j = 0; j < 7; j++) r[j + 1] = xs[c * 49 + ih * 7 + j];
            } else {
#pragma unroll
                for (int j = 0; j < 7; j++) r[j + 1] = 0.f;
            }
#pragma unroll
            for (int kw = 0; kw < 3; kw++) {
                float w0 = ws[((o * 32 + c) * 3 + kh) * 3 + kw];
                float w1 = ws[(((o + 32) * 32 + c) * 3 + kh) * 3 + kw];
#pragma unroll
                for (int p = 0; p < 7; p++) {
                    acc0[p] = fmaf(w0, r[p + kw], acc0[p]);
                    acc1[p] = fmaf(w1, r[p + kw], acc1[p]);
                }
            }
        }
    }
    float* vp0 = g_bufC + (size_t)t * 25088 + ((n * 64 + o) * 7 + oh) * 7;
    float* vp1 = g_bufC + (size_t)t * 25088 + ((n * 64 + o + 32) * 7 + oh) * 7;
#pragma unroll
    for (int p = 0; p < 7; p++) { vp0[p] = acc0[p]; vp1[p] = acc1[p]; }
}

// K4: dense head per timestep on psp5 floats: A -> Y[t][n][o].
__global__ void __launch_bounds__(256) k_fc(const float* __restrict__ w) {
    __shared__ float red[256];
    int b = blockIdx.x;
    int t = b >> 3;
    int n = b & 7;
    const float* xp = g_bufA + (size_t)t * 25088 + n * 3136;
    float acc[10];
#pragma unroll
    for (int o = 0; o < 10; o++) acc[o] = 0.f;
    for (int j = threadIdx.x; j < 3136; j += 256) {
        float xv = xp[j];
#pragma unroll
        for (int o = 0; o < 10; o++) acc[o] = fmaf(xv, w[o * 3136 + j], acc[o]);
    }
#pragma unroll
    for (int o = 0; o < 10; o++) {
        red[threadIdx.x] = acc[o];
        __syncthreads();
        for (int st = 128; st > 0; st >>= 1) {
            if (threadIdx.x < st) red[threadIdx.x] += red[threadIdx.x + st];
            __syncthreads();
        }
        if (threadIdx.x == 0) g_bufY[(size_t)t * 80 + n * 10 + o] = red[0];
        __syncthreads();
    }
}

// K5: final spike scan over 80 output neurons -> [8,10,300]
__global__ void k_spike_out(float* __restrict__ out) {
    int i = threadIdx.x;
    if (i >= 80) return;
    float ps = 0.f, qs = 0.f;
    for (int t = 0; t < TT; t++) {
        out[i * 300 + t] = spike_step(g_bufY[t * 80 + i], ps, qs);
    }
}

extern "C" void kernel_launch(void* const* d_in, const int* in_sizes, int n_in,
                              void* d_out, int out_size) {
    const float* x  = (const float*)d_in[0];   // [8,1,30,30,300]
    const float* w1 = (const float*)d_in[1];   // [16,1,5,5]
    const float* w2 = (const float*)d_in[2];   // [32,16,3,3]
    const float* w3 = (const float*)d_in[3];   // [64,32,3,3]
    const float* wf = (const float*)d_in[4];   // [10,64,7,7]
    float* out = (float*)d_out;

    float *bufA, *bufC, *bufD;
    cudaGetSymbolAddress((void**)&bufA, g_bufA);
    cudaGetSymbolAddress((void**)&bufC, g_bufC);
    cudaGetSymbolAddress((void**)&bufD, g_bufD);

    cudaFuncSetAttribute(k_conv3, cudaFuncAttributeMaxDynamicSharedMemorySize, 80000);

    k_psp0<<<(7200 + 127) / 128, 128>>>(x);                          // x -> D (psp0)
    k_conv1<<<2400, 448>>>(w1);                                      // D -> A (v1)
    k_fused_pool<<<(25088 + 127) / 128, 128>>>(bufA, bufC,
                                   16, 14, 14, 100352, 25088);       // A -> C (psp2)
    k_conv2<<<2400, 448>>>(w2);                                      // C -> A (v3)
    k_fused_pool<<<(12544 + 63) / 64, 64>>>(bufA, bufD,
                                   32, 7, 7, 50176, 12544);          // A -> D (psp4)
    k_conv3<<<2400, 224, 80000>>>(w3);                               // D -> C (v5)
    k_spike_psp<<<(25088 + 127) / 128, 128>>>(bufC, bufA, 25088);    // C -> A (psp5)
    k_fc<<<2400, 256>>>(wf);                                         // A -> Y
    k_spike_out<<<1, 128>>>(out);                                    // Y -> out
}